// round 6
// baseline (speedup 1.0000x reference)
#include <cuda_runtime.h>
#include <math.h>

#define BATCH 4096
#define NCLS 1000
#define DIM 512
#define QSZ 8192
#define INV_T (1.0f / 0.07f)
#define EPSP 1e-8f

// ---------------- scratch (__device__ globals; no allocations allowed) ------
__device__ float g_feat[BATCH * DIM];           // normalized embeddings      8 MB
__device__ float g_cent[NCLS * DIM];            // normalized centers         2 MB
__device__ float g_qp[QSZ * DIM];               // label-permuted queue      16 MB
__device__ float g_S[(size_t)BATCH * QSZ];      // feat @ queue_p^T / T     128 MB
__device__ float g_CS[(size_t)BATCH * NCLS];    // feat @ cent^T / T         16 MB
__device__ int   g_start[NCLS + 2];             // segment starts per class
__device__ int   g_perm[QSZ];                   // permutation (sorted by label)
__device__ double g_acc[2];                     // [0]=cls nll sum, [1]=contrastive nll sum

// ---------------- row L2 normalize (block per row, 128 threads) -------------
__global__ void norm_rows(const float* __restrict__ x, float* __restrict__ y) {
    int r = blockIdx.x;
    const float4* xr = (const float4*)(x + (size_t)r * DIM);
    float4 v = xr[threadIdx.x];
    float ss = v.x * v.x + v.y * v.y + v.z * v.z + v.w * v.w;
#pragma unroll
    for (int o = 16; o; o >>= 1) ss += __shfl_down_sync(0xffffffffu, ss, o);
    __shared__ float sh[4];
    if ((threadIdx.x & 31) == 0) sh[threadIdx.x >> 5] = ss;
    __syncthreads();
    float tot = sh[0] + sh[1] + sh[2] + sh[3];
    float inv = 1.0f / fmaxf(sqrtf(tot), 1e-12f);
    float4 o4 = make_float4(v.x * inv, v.y * inv, v.z * inv, v.w * inv);
    ((float4*)(y + (size_t)r * DIM))[threadIdx.x] = o4;
}

// ---------------- counting sort of queue labels (single block) --------------
__global__ void build_perm(const int* __restrict__ labels) {
    __shared__ int cnt[NCLS + 1];
    __shared__ int cur[NCLS + 1];
    int tid = threadIdx.x;
    for (int i = tid; i < NCLS + 1; i += blockDim.x) cnt[i] = 0;
    if (tid == 0) { g_acc[0] = 0.0; g_acc[1] = 0.0; }
    __syncthreads();
    for (int q = tid; q < QSZ; q += blockDim.x) {
        int l = labels[q];
        int b = (l >= 0 && l < NCLS) ? l : NCLS;
        atomicAdd(&cnt[b], 1);
    }
    __syncthreads();
    if (tid == 0) {
        int run = 0;
        for (int c = 0; c < NCLS + 1; c++) {
            cur[c] = run;
            g_start[c] = run;
            run += cnt[c];
        }
        g_start[NCLS + 1] = run;
    }
    __syncthreads();
    for (int q = tid; q < QSZ; q += blockDim.x) {
        int l = labels[q];
        int b = (l >= 0 && l < NCLS) ? l : NCLS;
        int p = atomicAdd(&cur[b], 1);
        g_perm[p] = q;
    }
}

// ---------------- gather queue rows into label-sorted order -----------------
__global__ void permute_queue(const float* __restrict__ queue) {
    int idx = blockIdx.x * blockDim.x + threadIdx.x;  // QSZ * 128 threads
    int r = idx >> 7, c = idx & 127;
    int src = g_perm[r];
    ((float4*)g_qp)[(size_t)r * 128 + c] =
        ((const float4*)queue)[(size_t)src * 128 + c];
}

// ---------------- SGEMM: C[m,n] = alpha * sum_k A[m,k]*B[n,k] ---------------
// A: [M,K] row-major, Bm: [N,K] row-major, C: [M,N] row-major. M%128==0, K%8==0.
#define GBM 128
#define GBN 128
#define GBK 8
#define GTM 8
#define GTN 8
__global__ __launch_bounds__(256) void gemm_nt(const float* __restrict__ A,
                                               const float* __restrict__ Bm,
                                               float* __restrict__ Cm,
                                               int N, int K, float alpha) {
    __shared__ float As[GBK][GBM];
    __shared__ float Bs[GBK][GBN];
    int bx = blockIdx.x;  // N tile
    int by = blockIdx.y;  // M tile
    int tid = threadIdx.x;
    int lr = tid >> 1;            // 0..127 : row within tile for loading
    int lc = (tid & 1) * 4;       // 0 or 4 : k offset for float4 load
    int trow = (tid >> 4) * GTM;  // 0..120
    int tcol = (tid & 15) * GTN;  // 0..120

    float acc[GTM][GTN] = {};
    const float* Ap = A + (size_t)(by * GBM + lr) * K + lc;
    const float* Bp = Bm + (size_t)(bx * GBN + lr) * K + lc;
    bool bvalid = (bx * GBN + lr) < N;

    for (int k0 = 0; k0 < K; k0 += GBK) {
        float4 av = *(const float4*)(Ap + k0);
        As[lc + 0][lr] = av.x; As[lc + 1][lr] = av.y;
        As[lc + 2][lr] = av.z; As[lc + 3][lr] = av.w;
        float4 bv = make_float4(0.f, 0.f, 0.f, 0.f);
        if (bvalid) bv = *(const float4*)(Bp + k0);
        Bs[lc + 0][lr] = bv.x; Bs[lc + 1][lr] = bv.y;
        Bs[lc + 2][lr] = bv.z; Bs[lc + 3][lr] = bv.w;
        __syncthreads();
#pragma unroll
        for (int k = 0; k < GBK; k++) {
            float ar[GTM], br[GTN];
#pragma unroll
            for (int i = 0; i < GTM; i++) ar[i] = As[k][trow + i];
#pragma unroll
            for (int j = 0; j < GTN; j++) br[j] = Bs[k][tcol + j];
#pragma unroll
            for (int i = 0; i < GTM; i++)
#pragma unroll
                for (int j = 0; j < GTN; j++) acc[i][j] = fmaf(ar[i], br[j], acc[i][j]);
        }
        __syncthreads();
    }
#pragma unroll
    for (int i = 0; i < GTM; i++) {
        int gm = by * GBM + trow + i;
#pragma unroll
        for (int j = 0; j < GTN; j++) {
            int gn = bx * GBN + tcol + j;
            if (gn < N) Cm[(size_t)gm * N + gn] = alpha * acc[i][j];
        }
    }
}

// ---------------- contrastive CE: one block per batch row -------------------
__global__ __launch_bounds__(256) void row_contrastive(const float* __restrict__ prior,
                                                       const int* __restrict__ targets,
                                                       const unsigned char* __restrict__ init) {
    int b = blockIdx.x, tid = threadIdx.x;
    const float* Srow = g_S + (size_t)b * QSZ;
    const float* CSrow = g_CS + (size_t)b * NCLS;
    int tgt = targets[b];
    __shared__ float sm[256], ssum[256];
    __shared__ float stv;
    float m = -INFINITY, s = 0.f;
    for (int c = tid; c < NCLS; c += 256) {
        int s0 = g_start[c], s1 = g_start[c + 1];
        int cnt = s1 - s0;
        float ql = 0.f;
        if (cnt > 0) {
            float mx = -INFINITY;
            for (int q = s0; q < s1; q++) mx = fmaxf(mx, Srow[q]);
            float se = 0.f;
            for (int q = s0; q < s1; q++) se += __expf(Srow[q] - mx);
            ql = mx + __logf(se) - __logf((float)cnt);
        }
        float cl = init[c] ? CSrow[c] : 0.f;
        float a = fmaxf(cl, ql), d = fminf(cl, ql);
        float comp = a + log1pf(__expf(d - a));            // logaddexp
        float v = comp - logf(fmaxf(prior[c], EPSP));      // - prior_adjust
        if (c == tgt) stv = v;
        if (v > m) { s = s * __expf(m - v) + 1.f; m = v; }
        else        { s += __expf(v - m); }
    }
    sm[tid] = m; ssum[tid] = s;
    __syncthreads();
    for (int o = 128; o; o >>= 1) {
        if (tid < o) {
            float m2 = sm[tid + o], s2 = ssum[tid + o];
            float M = fmaxf(sm[tid], m2);
            ssum[tid] = ssum[tid] * __expf(sm[tid] - M) + s2 * __expf(m2 - M);
            sm[tid] = M;
        }
        __syncthreads();
    }
    if (tid == 0) {
        float lse = sm[0] + __logf(ssum[0]);
        atomicAdd(&g_acc[1], (double)(lse - stv));
    }
}

// ---------------- plain classification CE: one block per batch row ----------
__global__ __launch_bounds__(256) void row_cls(const float* __restrict__ logits,
                                               const float* __restrict__ prior,
                                               const int* __restrict__ targets) {
    int b = blockIdx.x, tid = threadIdx.x;
    const float* L = logits + (size_t)b * NCLS;
    int tgt = targets[b];
    __shared__ float sm[256], ssum[256];
    __shared__ float stv;
    float m = -INFINITY, s = 0.f;
    for (int c = tid; c < NCLS; c += 256) {
        float v = L[c] - logf(fmaxf(prior[c], EPSP));
        if (c == tgt) stv = v;
        if (v > m) { s = s * __expf(m - v) + 1.f; m = v; }
        else        { s += __expf(v - m); }
    }
    sm[tid] = m; ssum[tid] = s;
    __syncthreads();
    for (int o = 128; o; o >>= 1) {
        if (tid < o) {
            float m2 = sm[tid + o], s2 = ssum[tid + o];
            float M = fmaxf(sm[tid], m2);
            ssum[tid] = ssum[tid] * __expf(sm[tid] - M) + s2 * __expf(m2 - M);
            sm[tid] = M;
        }
        __syncthreads();
    }
    if (tid == 0) {
        float lse = sm[0] + __logf(ssum[0]);
        atomicAdd(&g_acc[0], (double)(lse - stv));
    }
}

__global__ void finalize(float* out) {
    out[0] = (float)(1.0 * (g_acc[0] / BATCH) + 0.1 * (g_acc[1] / BATCH));
}

// ---------------- launch ----------------------------------------------------
extern "C" void kernel_launch(void* const* d_in, const int* in_sizes, int n_in,
                              void* d_out, int out_size) {
    const float* logits    = (const float*)d_in[0];          // [4096,1000]
    const float* embed     = (const float*)d_in[1];          // [4096,512]
    const float* centers   = (const float*)d_in[2];          // [1000,512]
    const float* queue     = (const float*)d_in[3];          // [8192,512]
    const float* prior     = (const float*)d_in[4];          // [1000]
    const int*   targets   = (const int*)d_in[5];            // [4096]
    const unsigned char* cinit = (const unsigned char*)d_in[6]; // [1000] bool
    const int*   qlabels   = (const int*)d_in[7];            // [8192]
    float* out = (float*)d_out;

    float* feat; cudaGetSymbolAddress((void**)&feat, g_feat);
    float* cent; cudaGetSymbolAddress((void**)&cent, g_cent);
    float* qp;   cudaGetSymbolAddress((void**)&qp,   g_qp);
    float* S;    cudaGetSymbolAddress((void**)&S,    g_S);
    float* CS;   cudaGetSymbolAddress((void**)&CS,   g_CS);

    norm_rows<<<BATCH, 128>>>(embed, feat);
    norm_rows<<<NCLS, 128>>>(centers, cent);
    build_perm<<<1, 1024>>>(qlabels);
    permute_queue<<<(QSZ * 128) / 256, 256>>>(queue);

    dim3 gS(QSZ / GBN, BATCH / GBM);
    gemm_nt<<<gS, 256>>>(feat, qp, S, QSZ, DIM, INV_T);
    dim3 gC((NCLS + GBN - 1) / GBN, BATCH / GBM);
    gemm_nt<<<gC, 256>>>(feat, cent, CS, NCLS, DIM, INV_T);

    row_contrastive<<<BATCH, 256>>>(prior, targets, cinit);
    row_cls<<<BATCH, 256>>>(logits, prior, targets);
    finalize<<<1, 1>>>(out);
}

// round 7
// speedup vs baseline: 2.2718x; 2.2718x over previous
#include <cuda_runtime.h>
#include <math.h>

#define BATCH 4096
#define NCLS 1000
#define DIM 512
#define QSZ 8192
#define INV_T (1.0f / 0.07f)
#define EPSP 1e-8f

// ---------------- scratch (__device__ globals; no allocations allowed) ------
__device__ float g_feat[BATCH * DIM];           // normalized embeddings
__device__ float g_cent[NCLS * DIM];            // normalized centers
__device__ float g_qp[QSZ * DIM];               // label-permuted queue
__device__ float g_S[(size_t)BATCH * QSZ];      // feat @ queue_p^T / T
__device__ float g_CS[(size_t)BATCH * NCLS];    // feat @ cent^T / T
__device__ int   g_start[NCLS + 2];
__device__ int   g_perm[QSZ];
__device__ double g_acc[2];

// ---------------- row L2 normalize ------------------------------------------
__global__ void norm_rows(const float* __restrict__ x, float* __restrict__ y) {
    int r = blockIdx.x;
    const float4* xr = (const float4*)(x + (size_t)r * DIM);
    float4 v = xr[threadIdx.x];
    float ss = v.x * v.x + v.y * v.y + v.z * v.z + v.w * v.w;
#pragma unroll
    for (int o = 16; o; o >>= 1) ss += __shfl_down_sync(0xffffffffu, ss, o);
    __shared__ float sh[4];
    if ((threadIdx.x & 31) == 0) sh[threadIdx.x >> 5] = ss;
    __syncthreads();
    float tot = sh[0] + sh[1] + sh[2] + sh[3];
    float inv = 1.0f / fmaxf(sqrtf(tot), 1e-12f);
    float4 o4 = make_float4(v.x * inv, v.y * inv, v.z * inv, v.w * inv);
    ((float4*)(y + (size_t)r * DIM))[threadIdx.x] = o4;
}

// ---------------- counting sort of queue labels (single block) --------------
__global__ void build_perm(const int* __restrict__ labels) {
    __shared__ int cnt[NCLS + 1];
    __shared__ int cur[NCLS + 1];
    int tid = threadIdx.x;
    for (int i = tid; i < NCLS + 1; i += blockDim.x) cnt[i] = 0;
    if (tid == 0) { g_acc[0] = 0.0; g_acc[1] = 0.0; }
    __syncthreads();
    for (int q = tid; q < QSZ; q += blockDim.x) {
        int l = labels[q];
        int b = (l >= 0 && l < NCLS) ? l : NCLS;
        atomicAdd(&cnt[b], 1);
    }
    __syncthreads();
    if (tid == 0) {
        int run = 0;
        for (int c = 0; c < NCLS + 1; c++) {
            cur[c] = run;
            g_start[c] = run;
            run += cnt[c];
        }
        g_start[NCLS + 1] = run;
    }
    __syncthreads();
    for (int q = tid; q < QSZ; q += blockDim.x) {
        int l = labels[q];
        int b = (l >= 0 && l < NCLS) ? l : NCLS;
        int p = atomicAdd(&cur[b], 1);
        g_perm[p] = q;
    }
}

// ---------------- gather queue rows into label-sorted order -----------------
__global__ void permute_queue(const float* __restrict__ queue) {
    int idx = blockIdx.x * blockDim.x + threadIdx.x;
    int r = idx >> 7, c = idx & 127;
    int src = g_perm[r];
    ((float4*)g_qp)[(size_t)r * 128 + c] =
        ((const float4*)queue)[(size_t)src * 128 + c];
}

// ---------------- tf32 tensor-core GEMM -------------------------------------
// C[m,n] = alpha * sum_k A[m,k]*B[n,k].  A:[M,K] rm, B:[N,K] rm, C:[M,N] rm.
// M%128==0, K%16==0. N arbitrary (guarded).
#define TBM 128
#define TBN 128
#define TBK 16
#define SPAD 6
#define SSTR (TBM + SPAD)   // 134 floats: conflict-free STS, ~2-way worst LDS

__device__ __forceinline__ unsigned f2tf(float x) {
    unsigned r;
    asm("cvt.rna.tf32.f32 %0, %1;" : "=r"(r) : "f"(x));
    return r;
}

__device__ __forceinline__ void mma_tf32(float c[4], const unsigned a[4], const unsigned b[2]) {
    asm volatile(
        "mma.sync.aligned.m16n8k8.row.col.f32.tf32.tf32.f32 "
        "{%0,%1,%2,%3}, {%4,%5,%6,%7}, {%8,%9}, {%0,%1,%2,%3};"
        : "+f"(c[0]), "+f"(c[1]), "+f"(c[2]), "+f"(c[3])
        : "r"(a[0]), "r"(a[1]), "r"(a[2]), "r"(a[3]), "r"(b[0]), "r"(b[1]));
}

__global__ __launch_bounds__(256) void gemm_tf32(const float* __restrict__ A,
                                                 const float* __restrict__ Bm,
                                                 float* __restrict__ Cm,
                                                 int N, int K, float alpha) {
    __shared__ float As[2][TBK][SSTR];
    __shared__ float Bs[2][TBK][SSTR];
    int tid = threadIdx.x;
    int bx = blockIdx.x, by = blockIdx.y;
    int wid = tid >> 5, lane = tid & 31;
    int gidq = lane >> 2, tig = lane & 3;
    int wm = (wid & 3) * 32;      // warp row offset (4 warps along M)
    int wn = (wid >> 2) * 64;     // warp col offset (2 warps along N)

    // global-load assignment: thread handles rows m0 and m0+64, k-quad kq
    int m0 = tid >> 2;            // 0..63
    int kq = tid & 3;             // float4 index within 16-wide k tile

    float acc[2][8][4];
#pragma unroll
    for (int i = 0; i < 2; i++)
#pragma unroll
        for (int j = 0; j < 8; j++)
#pragma unroll
            for (int r = 0; r < 4; r++) acc[i][j][r] = 0.f;

    const float* Abase = A + (size_t)(by * TBM) * K;
    const float* Bbase = Bm;
    int nrow0 = bx * TBN + m0;
    int nrow1 = nrow0 + 64;
    bool bv0 = nrow0 < N, bv1 = nrow1 < N;

    float4 ra0, ra1, rb0, rb1;
    // prologue: load tile 0
    {
        int kc = kq * 4;
        ra0 = *(const float4*)(Abase + (size_t)m0 * K + kc);
        ra1 = *(const float4*)(Abase + (size_t)(m0 + 64) * K + kc);
        rb0 = bv0 ? *(const float4*)(Bbase + (size_t)nrow0 * K + kc)
                  : make_float4(0.f, 0.f, 0.f, 0.f);
        rb1 = bv1 ? *(const float4*)(Bbase + (size_t)nrow1 * K + kc)
                  : make_float4(0.f, 0.f, 0.f, 0.f);
    }
    // store tile 0
    {
        int kr = kq * 4;
        As[0][kr + 0][m0] = __uint_as_float(f2tf(ra0.x));
        As[0][kr + 1][m0] = __uint_as_float(f2tf(ra0.y));
        As[0][kr + 2][m0] = __uint_as_float(f2tf(ra0.z));
        As[0][kr + 3][m0] = __uint_as_float(f2tf(ra0.w));
        As[0][kr + 0][m0 + 64] = __uint_as_float(f2tf(ra1.x));
        As[0][kr + 1][m0 + 64] = __uint_as_float(f2tf(ra1.y));
        As[0][kr + 2][m0 + 64] = __uint_as_float(f2tf(ra1.z));
        As[0][kr + 3][m0 + 64] = __uint_as_float(f2tf(ra1.w));
        Bs[0][kr + 0][m0] = __uint_as_float(f2tf(rb0.x));
        Bs[0][kr + 1][m0] = __uint_as_float(f2tf(rb0.y));
        Bs[0][kr + 2][m0] = __uint_as_float(f2tf(rb0.z));
        Bs[0][kr + 3][m0] = __uint_as_float(f2tf(rb0.w));
        Bs[0][kr + 0][m0 + 64] = __uint_as_float(f2tf(rb1.x));
        Bs[0][kr + 1][m0 + 64] = __uint_as_float(f2tf(rb1.y));
        Bs[0][kr + 2][m0 + 64] = __uint_as_float(f2tf(rb1.z));
        Bs[0][kr + 3][m0 + 64] = __uint_as_float(f2tf(rb1.w));
    }
    __syncthreads();

    int ntiles = K / TBK;
    int buf = 0;
    for (int kt = 0; kt < ntiles; kt++) {
        bool more = (kt + 1) < ntiles;
        if (more) {
            int kc = (kt + 1) * TBK + kq * 4;
            ra0 = *(const float4*)(Abase + (size_t)m0 * K + kc);
            ra1 = *(const float4*)(Abase + (size_t)(m0 + 64) * K + kc);
            rb0 = bv0 ? *(const float4*)(Bbase + (size_t)nrow0 * K + kc)
                      : make_float4(0.f, 0.f, 0.f, 0.f);
            rb1 = bv1 ? *(const float4*)(Bbase + (size_t)nrow1 * K + kc)
                      : make_float4(0.f, 0.f, 0.f, 0.f);
        }
#pragma unroll
        for (int ks = 0; ks < 2; ks++) {
            int k0 = ks * 8;
            unsigned afr[2][4], bfr[8][2];
#pragma unroll
            for (int i = 0; i < 2; i++) {
                int m = wm + i * 16 + gidq;
                afr[i][0] = __float_as_uint(As[buf][k0 + tig][m]);
                afr[i][1] = __float_as_uint(As[buf][k0 + tig][m + 8]);
                afr[i][2] = __float_as_uint(As[buf][k0 + tig + 4][m]);
                afr[i][3] = __float_as_uint(As[buf][k0 + tig + 4][m + 8]);
            }
#pragma unroll
            for (int j = 0; j < 8; j++) {
                int n = wn + j * 8 + gidq;
                bfr[j][0] = __float_as_uint(Bs[buf][k0 + tig][n]);
                bfr[j][1] = __float_as_uint(Bs[buf][k0 + tig + 4][n]);
            }
#pragma unroll
            for (int i = 0; i < 2; i++)
#pragma unroll
                for (int j = 0; j < 8; j++) mma_tf32(acc[i][j], afr[i], bfr[j]);
        }
        if (more) {
            int nb = buf ^ 1;
            int kr = kq * 4;
            As[nb][kr + 0][m0] = __uint_as_float(f2tf(ra0.x));
            As[nb][kr + 1][m0] = __uint_as_float(f2tf(ra0.y));
            As[nb][kr + 2][m0] = __uint_as_float(f2tf(ra0.z));
            As[nb][kr + 3][m0] = __uint_as_float(f2tf(ra0.w));
            As[nb][kr + 0][m0 + 64] = __uint_as_float(f2tf(ra1.x));
            As[nb][kr + 1][m0 + 64] = __uint_as_float(f2tf(ra1.y));
            As[nb][kr + 2][m0 + 64] = __uint_as_float(f2tf(ra1.z));
            As[nb][kr + 3][m0 + 64] = __uint_as_float(f2tf(ra1.w));
            Bs[nb][kr + 0][m0] = __uint_as_float(f2tf(rb0.x));
            Bs[nb][kr + 1][m0] = __uint_as_float(f2tf(rb0.y));
            Bs[nb][kr + 2][m0] = __uint_as_float(f2tf(rb0.z));
            Bs[nb][kr + 3][m0] = __uint_as_float(f2tf(rb0.w));
            Bs[nb][kr + 0][m0 + 64] = __uint_as_float(f2tf(rb1.x));
            Bs[nb][kr + 1][m0 + 64] = __uint_as_float(f2tf(rb1.y));
            Bs[nb][kr + 2][m0 + 64] = __uint_as_float(f2tf(rb1.z));
            Bs[nb][kr + 3][m0 + 64] = __uint_as_float(f2tf(rb1.w));
            __syncthreads();
            buf = nb;
        }
    }

    // epilogue
#pragma unroll
    for (int i = 0; i < 2; i++) {
        int row = by * TBM + wm + i * 16 + gidq;
#pragma unroll
        for (int j = 0; j < 8; j++) {
            int col = bx * TBN + wn + j * 8 + tig * 2;
            if (col + 1 < N) {
                float2 v0 = make_float2(alpha * acc[i][j][0], alpha * acc[i][j][1]);
                float2 v1 = make_float2(alpha * acc[i][j][2], alpha * acc[i][j][3]);
                *(float2*)(Cm + (size_t)row * N + col) = v0;
                *(float2*)(Cm + (size_t)(row + 8) * N + col) = v1;
            } else if (col < N) {
                Cm[(size_t)row * N + col] = alpha * acc[i][j][0];
                Cm[(size_t)(row + 8) * N + col] = alpha * acc[i][j][2];
            }
        }
    }
}

// ---------------- contrastive CE: one block per batch row -------------------
__global__ __launch_bounds__(256) void row_contrastive(const float* __restrict__ prior,
                                                       const int* __restrict__ targets,
                                                       const unsigned char* __restrict__ init) {
    int b = blockIdx.x, tid = threadIdx.x;
    const float* Srow = g_S + (size_t)b * QSZ;
    const float* CSrow = g_CS + (size_t)b * NCLS;
    int tgt = targets[b];
    __shared__ float sm[256], ssum[256];
    __shared__ float stv;
    float m = -INFINITY, s = 0.f;
    for (int c = tid; c < NCLS; c += 256) {
        int s0 = g_start[c], s1 = g_start[c + 1];
        int cnt = s1 - s0;
        float ql = 0.f;
        if (cnt > 0) {
            float mx = -INFINITY;
            for (int q = s0; q < s1; q++) mx = fmaxf(mx, Srow[q]);
            float se = 0.f;
            for (int q = s0; q < s1; q++) se += __expf(Srow[q] - mx);
            ql = mx + __logf(se) - __logf((float)cnt);
        }
        float cl = init[c] ? CSrow[c] : 0.f;
        float a = fmaxf(cl, ql), d = fminf(cl, ql);
        float comp = a + log1pf(__expf(d - a));
        float v = comp - logf(fmaxf(prior[c], EPSP));
        if (c == tgt) stv = v;
        if (v > m) { s = s * __expf(m - v) + 1.f; m = v; }
        else        { s += __expf(v - m); }
    }
    sm[tid] = m; ssum[tid] = s;
    __syncthreads();
    for (int o = 128; o; o >>= 1) {
        if (tid < o) {
            float m2 = sm[tid + o], s2 = ssum[tid + o];
            float M = fmaxf(sm[tid], m2);
            ssum[tid] = ssum[tid] * __expf(sm[tid] - M) + s2 * __expf(m2 - M);
            sm[tid] = M;
        }
        __syncthreads();
    }
    if (tid == 0) {
        float lse = sm[0] + __logf(ssum[0]);
        atomicAdd(&g_acc[1], (double)(lse - stv));
    }
}

// ---------------- plain classification CE -----------------------------------
__global__ __launch_bounds__(256) void row_cls(const float* __restrict__ logits,
                                               const float* __restrict__ prior,
                                               const int* __restrict__ targets) {
    int b = blockIdx.x, tid = threadIdx.x;
    const float* L = logits + (size_t)b * NCLS;
    int tgt = targets[b];
    __shared__ float sm[256], ssum[256];
    __shared__ float stv;
    float m = -INFINITY, s = 0.f;
    for (int c = tid; c < NCLS; c += 256) {
        float v = L[c] - logf(fmaxf(prior[c], EPSP));
        if (c == tgt) stv = v;
        if (v > m) { s = s * __expf(m - v) + 1.f; m = v; }
        else        { s += __expf(v - m); }
    }
    sm[tid] = m; ssum[tid] = s;
    __syncthreads();
    for (int o = 128; o; o >>= 1) {
        if (tid < o) {
            float m2 = sm[tid + o], s2 = ssum[tid + o];
            float M = fmaxf(sm[tid], m2);
            ssum[tid] = ssum[tid] * __expf(sm[tid] - M) + s2 * __expf(m2 - M);
            sm[tid] = M;
        }
        __syncthreads();
    }
    if (tid == 0) {
        float lse = sm[0] + __logf(ssum[0]);
        atomicAdd(&g_acc[0], (double)(lse - stv));
    }
}

__global__ void finalize(float* out) {
    out[0] = (float)(1.0 * (g_acc[0] / BATCH) + 0.1 * (g_acc[1] / BATCH));
}

// ---------------- launch ----------------------------------------------------
extern "C" void kernel_launch(void* const* d_in, const int* in_sizes, int n_in,
                              void* d_out, int out_size) {
    const float* logits    = (const float*)d_in[0];
    const float* embed     = (const float*)d_in[1];
    const float* centers   = (const float*)d_in[2];
    const float* queue     = (const float*)d_in[3];
    const float* prior     = (const float*)d_in[4];
    const int*   targets   = (const int*)d_in[5];
    const unsigned char* cinit = (const unsigned char*)d_in[6];
    const int*   qlabels   = (const int*)d_in[7];
    float* out = (float*)d_out;

    float* feat; cudaGetSymbolAddress((void**)&feat, g_feat);
    float* cent; cudaGetSymbolAddress((void**)&cent, g_cent);
    float* qp;   cudaGetSymbolAddress((void**)&qp,   g_qp);
    float* S;    cudaGetSymbolAddress((void**)&S,    g_S);
    float* CS;   cudaGetSymbolAddress((void**)&CS,   g_CS);

    norm_rows<<<BATCH, 128>>>(embed, feat);
    norm_rows<<<NCLS, 128>>>(centers, cent);
    build_perm<<<1, 1024>>>(qlabels);
    permute_queue<<<(QSZ * 128) / 256, 256>>>(queue);

    dim3 gS(QSZ / TBN, BATCH / TBM);
    gemm_tf32<<<gS, 256>>>(feat, qp, S, QSZ, DIM, INV_T);
    dim3 gC((NCLS + TBN - 1) / TBN, BATCH / TBM);
    gemm_tf32<<<gC, 256>>>(feat, cent, CS, NCLS, DIM, INV_T);

    row_contrastive<<<BATCH, 256>>>(prior, targets, cinit);
    row_cls<<<BATCH, 256>>>(logits, prior, targets);
    finalize<<<1, 1>>>(out);
}

// round 9
// speedup vs baseline: 3.4916x; 1.5370x over previous
#include <cuda_runtime.h>
#include <cuda_bf16.h>
#include <math.h>
#include <stdint.h>

#define BATCH 4096
#define NCLS 1000
#define DIM 512
#define QSZ 8192
#define INV_T (1.0f / 0.07f)
#define EPSP 1e-8f

// ---------------- scratch (__device__ globals; no allocations allowed) ------
__device__ __nv_bfloat16 g_featbf[BATCH * DIM];   // normalized embeddings (bf16)
__device__ __nv_bfloat16 g_centbf[NCLS * DIM];    // normalized centers (bf16)
__device__ __nv_bfloat16 g_qpbf[QSZ * DIM];       // label-permuted queue (bf16)
__device__ float g_S[(size_t)BATCH * QSZ];        // feat @ queue_p^T / T
__device__ float g_CS[(size_t)BATCH * NCLS];      // feat @ cent^T / T
__device__ int   g_start[NCLS + 2];
__device__ int   g_perm[QSZ];
__device__ double g_acc[2];

// ---------------- row L2 normalize -> bf16 -----------------------------------
__global__ void norm_rows_bf(const float* __restrict__ x, __nv_bfloat16* __restrict__ y) {
    int r = blockIdx.x;
    const float4* xr = (const float4*)(x + (size_t)r * DIM);
    float4 v = xr[threadIdx.x];
    float ss = v.x * v.x + v.y * v.y + v.z * v.z + v.w * v.w;
#pragma unroll
    for (int o = 16; o; o >>= 1) ss += __shfl_down_sync(0xffffffffu, ss, o);
    __shared__ float sh[4];
    if ((threadIdx.x & 31) == 0) sh[threadIdx.x >> 5] = ss;
    __syncthreads();
    float tot = sh[0] + sh[1] + sh[2] + sh[3];
    float inv = 1.0f / fmaxf(sqrtf(tot), 1e-12f);
    __nv_bfloat162 lo = __floats2bfloat162_rn(v.x * inv, v.y * inv);
    __nv_bfloat162 hi = __floats2bfloat162_rn(v.z * inv, v.w * inv);
    __nv_bfloat162* yr = (__nv_bfloat162*)(y + (size_t)r * DIM);
    yr[threadIdx.x * 2 + 0] = lo;
    yr[threadIdx.x * 2 + 1] = hi;
}

// ---------------- counting sort of queue labels (single block) --------------
__global__ void build_perm(const int* __restrict__ labels) {
    __shared__ int cnt[NCLS + 1];
    __shared__ int cur[NCLS + 1];
    int tid = threadIdx.x;
    for (int i = tid; i < NCLS + 1; i += blockDim.x) cnt[i] = 0;
    if (tid == 0) { g_acc[0] = 0.0; g_acc[1] = 0.0; }
    __syncthreads();
    for (int q = tid; q < QSZ; q += blockDim.x) {
        int l = labels[q];
        int b = (l >= 0 && l < NCLS) ? l : NCLS;
        atomicAdd(&cnt[b], 1);
    }
    __syncthreads();
    if (tid == 0) {
        int run = 0;
        for (int c = 0; c < NCLS + 1; c++) {
            cur[c] = run;
            g_start[c] = run;
            run += cnt[c];
        }
        g_start[NCLS + 1] = run;
    }
    __syncthreads();
    for (int q = tid; q < QSZ; q += blockDim.x) {
        int l = labels[q];
        int b = (l >= 0 && l < NCLS) ? l : NCLS;
        int p = atomicAdd(&cur[b], 1);
        g_perm[p] = q;
    }
}

// ---------------- gather queue rows into label-sorted order (f32 -> bf16) ---
__global__ void permute_queue_bf(const float* __restrict__ queue) {
    int idx = blockIdx.x * blockDim.x + threadIdx.x;  // QSZ*128
    int r = idx >> 7, c = idx & 127;
    int src = g_perm[r];
    float4 v = ((const float4*)queue)[(size_t)src * 128 + c];
    __nv_bfloat162 lo = __floats2bfloat162_rn(v.x, v.y);
    __nv_bfloat162 hi = __floats2bfloat162_rn(v.z, v.w);
    __nv_bfloat162* yr = (__nv_bfloat162*)(g_qpbf + (size_t)r * DIM);
    yr[c * 2 + 0] = lo;
    yr[c * 2 + 1] = hi;
}

// ---------------- bf16 register tensor-core GEMM -----------------------------
// C[m,n] = alpha * sum_k A[m,k]*B[n,k].  A:[M,K] bf16 rm, B:[N,K] bf16 rm,
// C:[M,N] f32 rm. M%128==0, K%32==0. N arbitrary (guarded).
// Block 128x128x32, 8 warps (4 along M x 2 along N), warp tile 32x64.
#define TBM 128
#define TBN 128
#define TBK 32
#define KP  (TBK / 2)       // 16 kpairs (uint32 = bf16x2)
#define SSTR 132            // uint32 stride: conflict-free STS quads

__device__ __forceinline__ void mma_bf16(float c[4], const uint32_t a[4], const uint32_t b[2]) {
    asm volatile(
        "mma.sync.aligned.m16n8k16.row.col.f32.bf16.bf16.f32 "
        "{%0,%1,%2,%3}, {%4,%5,%6,%7}, {%8,%9}, {%0,%1,%2,%3};"
        : "+f"(c[0]), "+f"(c[1]), "+f"(c[2]), "+f"(c[3])
        : "r"(a[0]), "r"(a[1]), "r"(a[2]), "r"(a[3]), "r"(b[0]), "r"(b[1]));
}

__global__ __launch_bounds__(256) void gemm_bf16(const __nv_bfloat16* __restrict__ A,
                                                 const __nv_bfloat16* __restrict__ Bm,
                                                 float* __restrict__ Cm,
                                                 int N, int K, float alpha) {
    __shared__ uint32_t As[2][KP][SSTR];
    __shared__ uint32_t Bs[2][KP][SSTR];
    int tid = threadIdx.x;
    int bx = blockIdx.x, by = blockIdx.y;
    int wid = tid >> 5, lane = tid & 31;
    int g = lane >> 2, t = lane & 3;
    int wm = (wid & 3) * 32;       // warp offset along M
    int wn = (wid >> 2) * 64;      // warp offset along N

    // global-load assignment: rows m0 and m0+64, 16B chunk ch (8 bf16 = 4 kpairs)
    int m0 = tid >> 2;             // 0..63
    int ch = tid & 3;              // 0..3

    float acc[2][8][4];
#pragma unroll
    for (int i = 0; i < 2; i++)
#pragma unroll
        for (int j = 0; j < 8; j++)
#pragma unroll
            for (int r = 0; r < 4; r++) acc[i][j][r] = 0.f;

    const __nv_bfloat16* Abase = A + (size_t)(by * TBM) * K;
    int nrow0 = bx * TBN + m0;
    int nrow1 = nrow0 + 64;
    bool bv0 = nrow0 < N, bv1 = nrow1 < N;

    uint4 ra0, ra1, rb0, rb1;
    // prologue: load k-tile 0
    {
        int kc = ch * 8;
        ra0 = *(const uint4*)(Abase + (size_t)m0 * K + kc);
        ra1 = *(const uint4*)(Abase + (size_t)(m0 + 64) * K + kc);
        rb0 = bv0 ? *(const uint4*)(Bm + (size_t)nrow0 * K + kc) : make_uint4(0, 0, 0, 0);
        rb1 = bv1 ? *(const uint4*)(Bm + (size_t)nrow1 * K + kc) : make_uint4(0, 0, 0, 0);
    }
    {
        int kp = ch * 4;
        As[0][kp + 0][m0] = ra0.x; As[0][kp + 1][m0] = ra0.y;
        As[0][kp + 2][m0] = ra0.z; As[0][kp + 3][m0] = ra0.w;
        As[0][kp + 0][m0 + 64] = ra1.x; As[0][kp + 1][m0 + 64] = ra1.y;
        As[0][kp + 2][m0 + 64] = ra1.z; As[0][kp + 3][m0 + 64] = ra1.w;
        Bs[0][kp + 0][m0] = rb0.x; Bs[0][kp + 1][m0] = rb0.y;
        Bs[0][kp + 2][m0] = rb0.z; Bs[0][kp + 3][m0] = rb0.w;
        Bs[0][kp + 0][m0 + 64] = rb1.x; Bs[0][kp + 1][m0 + 64] = rb1.y;
        Bs[0][kp + 2][m0 + 64] = rb1.z; Bs[0][kp + 3][m0 + 64] = rb1.w;
    }
    __syncthreads();

    int ntiles = K / TBK;
    int buf = 0;
    for (int kt = 0; kt < ntiles; kt++) {
        bool more = (kt + 1) < ntiles;
        if (more) {
            int kc = (kt + 1) * TBK + ch * 8;
            ra0 = *(const uint4*)(Abase + (size_t)m0 * K + kc);
            ra1 = *(const uint4*)(Abase + (size_t)(m0 + 64) * K + kc);
            rb0 = bv0 ? *(const uint4*)(Bm + (size_t)nrow0 * K + kc) : make_uint4(0, 0, 0, 0);
            rb1 = bv1 ? *(const uint4*)(Bm + (size_t)nrow1 * K + kc) : make_uint4(0, 0, 0, 0);
        }
#pragma unroll
        for (int ks = 0; ks < 2; ks++) {
            int ko = ks * 8;   // kpair offset of this k16 half
            uint32_t afr[2][4], bfr[8][2];
#pragma unroll
            for (int i = 0; i < 2; i++) {
                int m = wm + i * 16 + g;
                afr[i][0] = As[buf][ko + t][m];
                afr[i][1] = As[buf][ko + t][m + 8];
                afr[i][2] = As[buf][ko + t + 4][m];
                afr[i][3] = As[buf][ko + t + 4][m + 8];
            }
#pragma unroll
            for (int j = 0; j < 8; j++) {
                int n = wn + j * 8 + g;
                bfr[j][0] = Bs[buf][ko + t][n];
                bfr[j][1] = Bs[buf][ko + t + 4][n];
            }
#pragma unroll
            for (int i = 0; i < 2; i++)
#pragma unroll
                for (int j = 0; j < 8; j++) mma_bf16(acc[i][j], afr[i], bfr[j]);
        }
        if (more) {
            int nb = buf ^ 1;
            int kp = ch * 4;
            As[nb][kp + 0][m0] = ra0.x; As[nb][kp + 1][m0] = ra0.y;
            As[nb][kp + 2][m0] = ra0.z; As[nb][kp + 3][m0] = ra0.w;
            As[nb][kp + 0][m0 + 64] = ra1.x; As[nb][kp + 1][m0 + 64] = ra1.y;
            As[nb][kp + 2][m0 + 64] = ra1.z; As[nb][kp + 3][m0 + 64] = ra1.w;
            Bs[nb][kp + 0][m0] = rb0.x; Bs[nb][kp + 1][m0] = rb0.y;
            Bs[nb][kp + 2][m0] = rb0.z; Bs[nb][kp + 3][m0] = rb0.w;
            Bs[nb][kp + 0][m0 + 64] = rb1.x; Bs[nb][kp + 1][m0 + 64] = rb1.y;
            Bs[nb][kp + 2][m0 + 64] = rb1.z; Bs[nb][kp + 3][m0 + 64] = rb1.w;
            __syncthreads();
            buf = nb;
        }
    }

    // epilogue: c0,c1 -> (row, col..col+1); c2,c3 -> (row+8, col..col+1)
#pragma unroll
    for (int i = 0; i < 2; i++) {
        int row = by * TBM + wm + i * 16 + g;
#pragma unroll
        for (int j = 0; j < 8; j++) {
            int col = bx * TBN + wn + j * 8 + t * 2;
            if (col + 1 < N) {
                float2 v0 = make_float2(alpha * acc[i][j][0], alpha * acc[i][j][1]);
                float2 v1 = make_float2(alpha * acc[i][j][2], alpha * acc[i][j][3]);
                *(float2*)(Cm + (size_t)row * N + col) = v0;
                *(float2*)(Cm + (size_t)(row + 8) * N + col) = v1;
            } else if (col < N) {
                Cm[(size_t)row * N + col] = alpha * acc[i][j][0];
                Cm[(size_t)(row + 8) * N + col] = alpha * acc[i][j][2];
            }
        }
    }
}

// ---------------- contrastive CE: one block per batch row -------------------
__global__ __launch_bounds__(256) void row_contrastive(const float* __restrict__ prior,
                                                       const int* __restrict__ targets,
                                                       const unsigned char* __restrict__ init) {
    int b = blockIdx.x, tid = threadIdx.x;
    const float* Srow = g_S + (size_t)b * QSZ;
    const float* CSrow = g_CS + (size_t)b * NCLS;
    int tgt = targets[b];
    __shared__ float sm[256], ssum[256];
    __shared__ float stv;
    float m = -INFINITY, s = 0.f;
    for (int c = tid; c < NCLS; c += 256) {
        int s0 = g_start[c], s1 = g_start[c + 1];
        int cnt = s1 - s0;
        float ql = 0.f;
        if (cnt > 0) {
            float mx = -INFINITY;
            for (int q = s0; q < s1; q++) mx = fmaxf(mx, Srow[q]);
            float se = 0.f;
            for (int q = s0; q < s1; q++) se += __expf(Srow[q] - mx);
            ql = mx + __logf(se) - __logf((float)cnt);
        }
        float cl = init[c] ? CSrow[c] : 0.f;
        float a = fmaxf(cl, ql), d = fminf(cl, ql);
        float comp = a + log1pf(__expf(d - a));
        float v = comp - logf(fmaxf(prior[c], EPSP));
        if (c == tgt) stv = v;
        if (v > m) { s = s * __expf(m - v) + 1.f; m = v; }
        else        { s += __expf(v - m); }
    }
    sm[tid] = m; ssum[tid] = s;
    __syncthreads();
    for (int o = 128; o; o >>= 1) {
        if (tid < o) {
            float m2 = sm[tid + o], s2 = ssum[tid + o];
            float M = fmaxf(sm[tid], m2);
            ssum[tid] = ssum[tid] * __expf(sm[tid] - M) + s2 * __expf(m2 - M);
            sm[tid] = M;
        }
        __syncthreads();
    }
    if (tid == 0) {
        float lse = sm[0] + __logf(ssum[0]);
        atomicAdd(&g_acc[1], (double)(lse - stv));
    }
}

// ---------------- plain classification CE -----------------------------------
__global__ __launch_bounds__(256) void row_cls(const float* __restrict__ logits,
                                               const float* __restrict__ prior,
                                               const int* __restrict__ targets) {
    int b = blockIdx.x, tid = threadIdx.x;
    const float* L = logits + (size_t)b * NCLS;
    int tgt = targets[b];
    __shared__ float sm[256], ssum[256];
    __shared__ float stv;
    float m = -INFINITY, s = 0.f;
    for (int c = tid; c < NCLS; c += 256) {
        float v = L[c] - logf(fmaxf(prior[c], EPSP));
        if (c == tgt) stv = v;
        if (v > m) { s = s * __expf(m - v) + 1.f; m = v; }
        else        { s += __expf(v - m); }
    }
    sm[tid] = m; ssum[tid] = s;
    __syncthreads();
    for (int o = 128; o; o >>= 1) {
        if (tid < o) {
            float m2 = sm[tid + o], s2 = ssum[tid + o];
            float M = fmaxf(sm[tid], m2);
            ssum[tid] = ssum[tid] * __expf(sm[tid] - M) + s2 * __expf(m2 - M);
            sm[tid] = M;
        }
        __syncthreads();
    }
    if (tid == 0) {
        float lse = sm[0] + __logf(ssum[0]);
        atomicAdd(&g_acc[0], (double)(lse - stv));
    }
}

__global__ void finalize(float* out) {
    out[0] = (float)(1.0 * (g_acc[0] / BATCH) + 0.1 * (g_acc[1] / BATCH));
}

// ---------------- launch ----------------------------------------------------
extern "C" void kernel_launch(void* const* d_in, const int* in_sizes, int n_in,
                              void* d_out, int out_size) {
    const float* logits    = (const float*)d_in[0];
    const float* embed     = (const float*)d_in[1];
    const float* centers   = (const float*)d_in[2];
    const float* queue     = (const float*)d_in[3];
    const float* prior     = (const float*)d_in[4];
    const int*   targets   = (const int*)d_in[5];
    const unsigned char* cinit = (const unsigned char*)d_in[6];
    const int*   qlabels   = (const int*)d_in[7];
    float* out = (float*)d_out;

    __nv_bfloat16* featbf; cudaGetSymbolAddress((void**)&featbf, g_featbf);
    __nv_bfloat16* centbf; cudaGetSymbolAddress((void**)&centbf, g_centbf);
    __nv_bfloat16* qpbf;   cudaGetSymbolAddress((void**)&qpbf,   g_qpbf);
    float* S;  cudaGetSymbolAddress((void**)&S,  g_S);
    float* CS; cudaGetSymbolAddress((void**)&CS, g_CS);

    norm_rows_bf<<<BATCH, 128>>>(embed, featbf);
    norm_rows_bf<<<NCLS, 128>>>(centers, centbf);
    build_perm<<<1, 1024>>>(qlabels);
    permute_queue_bf<<<(QSZ * 128) / 256, 256>>>(queue);

    dim3 gS(QSZ / TBN, BATCH / TBM);
    gemm_bf16<<<gS, 256>>>(featbf, qpbf, S, QSZ, DIM, INV_T);
    dim3 gC((NCLS + TBN - 1) / TBN, BATCH / TBM);
    gemm_bf16<<<gC, 256>>>(featbf, centbf, CS, NCLS, DIM, INV_T);

    row_contrastive<<<BATCH, 256>>>(prior, targets, cinit);
    row_cls<<<BATCH, 256>>>(logits, prior, targets);
    finalize<<<1, 1>>>(out);
}